// round 15
// baseline (speedup 1.0000x reference)
#include <cuda_runtime.h>
#include <cuda_bf16.h>
#include <cstdint>

// Problem constants
#define BATCH 2
#define SEQ   2048
#define EMB   1024
#define NH    16
#define DH    64
#define WIN   128

// ---------------------------------------------------------------------------
// Scratch (static __device__ globals -- allocation-free)
// ---------------------------------------------------------------------------
__device__ float g_Q[BATCH * NH * SEQ * DH];   // [B,H,S,dh]
__device__ float g_K[BATCH * NH * SEQ * DH];
__device__ float g_V[BATCH * NH * SEQ * DH];
__device__ float g_ctx[BATCH * SEQ * EMB];     // [B,S,D]

__device__ __nv_bfloat16 g_xhi[BATCH * SEQ * EMB];
__device__ __nv_bfloat16 g_xlo[BATCH * SEQ * EMB];
__device__ __nv_bfloat16 g_whi[4 * EMB * EMB];   // Wq,Wk,Wv,Wo hi parts
__device__ __nv_bfloat16 g_wlo[4 * EMB * EMB];
__device__ __nv_bfloat16 g_chi[BATCH * SEQ * EMB];
__device__ __nv_bfloat16 g_clo[BATCH * SEQ * EMB];

// ---------------------------------------------------------------------------
// Helpers (all plain-target PTX: ldmatrix / mma.sync / cp.async)
// ---------------------------------------------------------------------------
__device__ __forceinline__ uint32_t smem_u32(const void* p) {
    uint32_t a;
    asm("{ .reg .u64 t; cvta.to.shared.u64 t, %1; cvt.u32.u64 %0, t; }"
        : "=r"(a) : "l"(p));
    return a;
}

__device__ __forceinline__ void cp_async16(uint32_t dst, const void* src) {
    asm volatile("cp.async.cg.shared.global [%0], [%1], 16;\n"
                 :: "r"(dst), "l"(src));
}

__device__ __forceinline__ void ldsm_x4(uint32_t addr, uint32_t* r) {
    asm volatile("ldmatrix.sync.aligned.m8n8.x4.shared.b16 {%0,%1,%2,%3}, [%4];"
                 : "=r"(r[0]), "=r"(r[1]), "=r"(r[2]), "=r"(r[3]) : "r"(addr));
}

__device__ __forceinline__ void ldsm_x2(uint32_t addr, uint32_t* r) {
    asm volatile("ldmatrix.sync.aligned.m8n8.x2.shared.b16 {%0,%1}, [%2];"
                 : "=r"(r[0]), "=r"(r[1]) : "r"(addr));
}

__device__ __forceinline__ void mma16816(float* c, const uint32_t* a, const uint32_t* b) {
    asm volatile(
        "mma.sync.aligned.m16n8k16.row.col.f32.bf16.bf16.f32 "
        "{%0,%1,%2,%3}, {%4,%5,%6,%7}, {%8,%9}, {%0,%1,%2,%3};\n"
        : "+f"(c[0]), "+f"(c[1]), "+f"(c[2]), "+f"(c[3])
        : "r"(a[0]), "r"(a[1]), "r"(a[2]), "r"(a[3]), "r"(b[0]), "r"(b[1]));
}

// ---------------------------------------------------------------------------
// fp32 -> (hi, lo) bf16 split
// ---------------------------------------------------------------------------
__global__ void __launch_bounds__(256)
split_bf16(const float* __restrict__ in, __nv_bfloat16* __restrict__ hi,
           __nv_bfloat16* __restrict__ lo, int n4)
{
    int i = blockIdx.x * blockDim.x + threadIdx.x;
    if (i >= n4) return;
    float4 v = *(const float4*)(in + 4 * (size_t)i);
    __nv_bfloat16 h0 = __float2bfloat16(v.x);
    __nv_bfloat16 h1 = __float2bfloat16(v.y);
    __nv_bfloat16 h2 = __float2bfloat16(v.z);
    __nv_bfloat16 h3 = __float2bfloat16(v.w);
    __nv_bfloat16 l0 = __float2bfloat16(v.x - __bfloat162float(h0));
    __nv_bfloat16 l1 = __float2bfloat16(v.y - __bfloat162float(h1));
    __nv_bfloat16 l2 = __float2bfloat16(v.z - __bfloat162float(h2));
    __nv_bfloat16 l3 = __float2bfloat16(v.w - __bfloat162float(h3));
    __nv_bfloat162* hp = (__nv_bfloat162*)(hi + 4 * (size_t)i);
    __nv_bfloat162* lp = (__nv_bfloat162*)(lo + 4 * (size_t)i);
    hp[0] = __nv_bfloat162(h0, h1);
    hp[1] = __nv_bfloat162(h2, h3);
    lp[0] = __nv_bfloat162(l0, l1);
    lp[1] = __nv_bfloat162(l2, l3);
}

// Fused 4-matrix weight split (Wq,Wk,Wv,Wo) -- grid.y = matrix index
__global__ void __launch_bounds__(256)
split_bf16_w4(const float* __restrict__ w0, const float* __restrict__ w1,
              const float* __restrict__ w2, const float* __restrict__ w3,
              __nv_bfloat16* __restrict__ hi, __nv_bfloat16* __restrict__ lo, int n4)
{
    int i = blockIdx.x * blockDim.x + threadIdx.x;
    if (i >= n4) return;
    const int mat = blockIdx.y;
    const float* in = (mat == 0) ? w0 : (mat == 1) ? w1 : (mat == 2) ? w2 : w3;
    hi += (size_t)mat * (4 * (size_t)n4);
    lo += (size_t)mat * (4 * (size_t)n4);
    float4 v = *(const float4*)(in + 4 * (size_t)i);
    __nv_bfloat16 h0 = __float2bfloat16(v.x);
    __nv_bfloat16 h1 = __float2bfloat16(v.y);
    __nv_bfloat16 h2 = __float2bfloat16(v.z);
    __nv_bfloat16 h3 = __float2bfloat16(v.w);
    __nv_bfloat16 l0 = __float2bfloat16(v.x - __bfloat162float(h0));
    __nv_bfloat16 l1 = __float2bfloat16(v.y - __bfloat162float(h1));
    __nv_bfloat16 l2 = __float2bfloat16(v.z - __bfloat162float(h2));
    __nv_bfloat16 l3 = __float2bfloat16(v.w - __bfloat162float(h3));
    __nv_bfloat162* hp = (__nv_bfloat162*)(hi + 4 * (size_t)i);
    __nv_bfloat162* lp = (__nv_bfloat162*)(lo + 4 * (size_t)i);
    hp[0] = __nv_bfloat162(h0, h1);
    hp[1] = __nv_bfloat162(h2, h3);
    lp[0] = __nv_bfloat162(l0, l1);
    lp[1] = __nv_bfloat162(l2, l3);
}

// ---------------------------------------------------------------------------
// Split-bf16 tensor-core GEMM core (mma.sync m16n8k16)
// CTA tile 128x128, BK=32, 8 warps (warp tile 64x32), cp.async double buffer.
// ---------------------------------------------------------------------------
#define LDT 40                      // bf16 elems per smem row (80B, LDSM conflict-free)
#define T_AH 0
#define T_AL (128 * LDT)
#define T_WH (2 * 128 * LDT)
#define T_WL (3 * 128 * LDT)
#define SSTAGE (4 * 128 * LDT)      // bf16 elems per stage (40960 B)

// MODE 0: row-major out;  MODE 1: scatter to [B,H,S,dh]
template <int MODE>
__device__ __forceinline__ void gemm_core(
    const __nv_bfloat16* __restrict__ Ahi, const __nv_bfloat16* __restrict__ Alo,
    const __nv_bfloat16* __restrict__ Whi, const __nv_bfloat16* __restrict__ Wlo,
    const float* __restrict__ bias, float* __restrict__ C,
    int m0, int n0, __nv_bfloat16* smem)
{
    constexpr int KD  = EMB;         // 1024
    constexpr int NCH = KD / 32;     // 32 K-chunks

    const uint32_t sbase = smem_u32(smem);
    const int tid  = threadIdx.x;
    const int wid  = tid >> 5;
    const int lane = tid & 31;

    const int glr = tid >> 2;            // 0..63
    const int glc = (tid & 3) * 8;       // bf16 col 0,8,16,24

    auto load_chunk = [&](int c, int stg) {
        const int k0 = c * 32;
        const uint32_t sb = sbase + (uint32_t)stg * (SSTAGE * 2);
#pragma unroll
        for (int p = 0; p < 2; p++) {
            const int row = glr + 64 * p;
            const size_t ga = (size_t)(m0 + row) * KD + k0 + glc;
            const size_t gw = (size_t)(n0 + row) * KD + k0 + glc;
            const uint32_t so = (uint32_t)(row * LDT + glc) * 2;
            cp_async16(sb + T_AH * 2 + so, Ahi + ga);
            cp_async16(sb + T_AL * 2 + so, Alo + ga);
            cp_async16(sb + T_WH * 2 + so, Whi + gw);
            cp_async16(sb + T_WL * 2 + so, Wlo + gw);
        }
    };

    float acc[4][4][4];
#pragma unroll
    for (int i = 0; i < 4; i++)
#pragma unroll
        for (int j = 0; j < 4; j++)
#pragma unroll
            for (int e = 0; e < 4; e++) acc[i][j][e] = 0.f;

    const int wm = wid >> 2;             // 0..1  (M)
    const int wn = wid & 3;              // 0..3  (N)
    const int mbase = wm * 64;
    const int nbase = wn * 32;

    const int a_row = mbase + (lane & 15);
    const int a_kad = 8 * (lane >> 4);
    const int b_row = nbase + (lane & 7);
    const int b_kad = 8 * ((lane >> 3) & 1);

    load_chunk(0, 0);
    asm volatile("cp.async.commit_group;\n");

    for (int c = 0; c < NCH; c++) {
        if (c + 1 < NCH) {
            load_chunk(c + 1, (c + 1) & 1);
            asm volatile("cp.async.commit_group;\n");
            asm volatile("cp.async.wait_group 1;\n");
        } else {
            asm volatile("cp.async.wait_group 0;\n");
        }
        __syncthreads();

        const uint32_t sb = sbase + (uint32_t)(c & 1) * (SSTAGE * 2);
#pragma unroll
        for (int ks = 0; ks < 2; ks++) {
            const int kk = ks * 16;
            uint32_t ah[4][4], al[4][4];
#pragma unroll
            for (int i = 0; i < 4; i++) {
                const uint32_t ao =
                    (uint32_t)((a_row + i * 16) * LDT + kk + a_kad) * 2;
                ldsm_x4(sb + T_AH * 2 + ao, ah[i]);
                ldsm_x4(sb + T_AL * 2 + ao, al[i]);
            }
#pragma unroll
            for (int j = 0; j < 4; j++) {
                uint32_t bh[2], bl[2];
                const uint32_t bo =
                    (uint32_t)((b_row + j * 8) * LDT + kk + b_kad) * 2;
                ldsm_x2(sb + T_WH * 2 + bo, bh);
                ldsm_x2(sb + T_WL * 2 + bo, bl);
#pragma unroll
                for (int i = 0; i < 4; i++) {
                    mma16816(acc[i][j], ah[i], bh);
                    mma16816(acc[i][j], ah[i], bl);
                    mma16816(acc[i][j], al[i], bh);
                }
            }
        }
        __syncthreads();
    }

    // ---- epilogue ----
    const int qr = lane >> 2;            // 0..7
    const int qc = (lane & 3) * 2;       // 0,2,4,6
#pragma unroll
    for (int i = 0; i < 4; i++) {
#pragma unroll
        for (int j = 0; j < 4; j++) {
            const int n = n0 + nbase + j * 8 + qc;
            const float b0 = bias[n], b1 = bias[n + 1];
#pragma unroll
            for (int half = 0; half < 2; half++) {
                const int m = m0 + mbase + i * 16 + qr + half * 8;
                float2 v;
                v.x = acc[i][j][half * 2 + 0] + b0;
                v.y = acc[i][j][half * 2 + 1] + b1;
                if (MODE == 0) {
                    *(float2*)(C + (size_t)m * EMB + n) = v;
                } else {
                    const int b  = m >> 11;     // SEQ = 2048
                    const int s  = m & 2047;
                    const int h  = n >> 6;      // DH = 64
                    const int d0 = n & 63;
                    *(float2*)(C + (((size_t)(b * NH + h)) * SEQ + s) * DH + d0) = v;
                }
            }
        }
    }
}

// Fused QKV projection: grid.x = 24 (mat*8 + nblock), grid.y = 32 (m blocks)
__global__ void __launch_bounds__(256, 2)
gemm_mma_qkv(const __nv_bfloat16* __restrict__ Ahi, const __nv_bfloat16* __restrict__ Alo,
             const __nv_bfloat16* __restrict__ WhiAll, const __nv_bfloat16* __restrict__ WloAll,
             const float* __restrict__ bq, const float* __restrict__ bk,
             const float* __restrict__ bv,
             float* __restrict__ Qd, float* __restrict__ Kd, float* __restrict__ Vd)
{
    extern __shared__ __nv_bfloat16 smem[];
    const int mat = blockIdx.x >> 3;
    const int n0  = (blockIdx.x & 7) * 128;
    const int m0  = blockIdx.y * 128;
    const __nv_bfloat16* Whi = WhiAll + (size_t)mat * (EMB * EMB);
    const __nv_bfloat16* Wlo = WloAll + (size_t)mat * (EMB * EMB);
    const float* bias = (mat == 0) ? bq : (mat == 1) ? bk : bv;
    float* C = (mat == 0) ? Qd : (mat == 1) ? Kd : Vd;
    gemm_core<1>(Ahi, Alo, Whi, Wlo, bias, C, m0, n0, smem);
}

// Output projection (row-major out)
__global__ void __launch_bounds__(256, 2)
gemm_mma_o(const __nv_bfloat16* __restrict__ Ahi, const __nv_bfloat16* __restrict__ Alo,
           const __nv_bfloat16* __restrict__ Whi, const __nv_bfloat16* __restrict__ Wlo,
           const float* __restrict__ bias, float* __restrict__ C)
{
    extern __shared__ __nv_bfloat16 smem[];
    gemm_core<0>(Ahi, Alo, Whi, Wlo, bias, C, blockIdx.y * 128, blockIdx.x * 128, smem);
}

// ---------------------------------------------------------------------------
// Banded attention: 512 threads/CTA (16 warps), per-thread microtile 2x4.
// One CTA = 64 queries of one (b,h); 320-key window; full softmax in smem.
// ---------------------------------------------------------------------------
__global__ void __launch_bounds__(512, 1)
attn_kernel(const float* __restrict__ Q, const float* __restrict__ K,
            const float* __restrict__ V, float* __restrict__ ctx,
            float* __restrict__ attn, int writeAttn)
{
    constexpr int BQ = 64;
    constexpr int KW = 2 * WIN + BQ;   // 320
    constexpr int PS = KW + 1;         // 321
    constexpr int LD = 68;

    extern __shared__ float smf[];
    float* Qs = smf;                    // [DH][LD] d-major
    float* Ts = smf + DH * LD;          // K phase d-major; V phase k-major
    float* Ss = smf + 2 * DH * LD;      // [BQ][PS]

    const int tid = threadIdx.x;
    const int tx = tid & 15;            // 0..15 (n, 4-wide)
    const int ty = tid >> 4;            // 0..31 (m, 2-wide)
    const int qt = blockIdx.x, h = blockIdx.y, b = blockIdx.z;
    const int q0 = qt * BQ;
    const int kstart = q0 - WIN;

    const float* Qb = Q + ((size_t)(b * NH + h) * SEQ + q0) * DH;
    const float* Kb = K + (size_t)(b * NH + h) * SEQ * DH;
    const float* Vb = V + (size_t)(b * NH + h) * SEQ * DH;

    // Load Q tile transposed: Qs[d][q]  (1024 float4 loads, 512 threads x2)
#pragma unroll
    for (int i = 0; i < 2; i++) {
        const int idx = tid + i * 512;
        const int row = idx >> 4;
        const int c4 = (idx & 15) << 2;
        float4 v = *(const float4*)(Qb + row * DH + c4);
        Qs[(c4 + 0) * LD + row] = v.x;
        Qs[(c4 + 1) * LD + row] = v.y;
        Qs[(c4 + 2) * LD + row] = v.z;
        Qs[(c4 + 3) * LD + row] = v.w;
    }
    __syncthreads();

    // ---- Phase 1: scores ----
    for (int t = 0; t < 5; t++) {
        const int kg0 = kstart + t * 64;
#pragma unroll
        for (int i = 0; i < 2; i++) {
            const int idx = tid + i * 512;
            const int row = idx >> 4;
            const int c4 = (idx & 15) << 2;
            const int kr = kg0 + row;
            float4 v = make_float4(0.f, 0.f, 0.f, 0.f);
            if (kr >= 0 && kr < SEQ)
                v = *(const float4*)(Kb + (size_t)kr * DH + c4);
            Ts[(c4 + 0) * LD + row] = v.x;
            Ts[(c4 + 1) * LD + row] = v.y;
            Ts[(c4 + 2) * LD + row] = v.z;
            Ts[(c4 + 3) * LD + row] = v.w;
        }
        __syncthreads();

        float acc[2][4];
#pragma unroll
        for (int i = 0; i < 2; i++)
#pragma unroll
            for (int j = 0; j < 4; j++) acc[i][j] = 0.f;

#pragma unroll 8
        for (int d = 0; d < DH; d++) {
            float2 av = *(const float2*)&Qs[d * LD + (ty << 1)];
            float4 bv = *(const float4*)&Ts[d * LD + (tx << 2)];
            acc[0][0] += av.x * bv.x; acc[0][1] += av.x * bv.y;
            acc[0][2] += av.x * bv.z; acc[0][3] += av.x * bv.w;
            acc[1][0] += av.y * bv.x; acc[1][1] += av.y * bv.y;
            acc[1][2] += av.y * bv.z; acc[1][3] += av.y * bv.w;
        }
#pragma unroll
        for (int i = 0; i < 2; i++)
#pragma unroll
            for (int j = 0; j < 4; j++)
                Ss[((ty << 1) + i) * PS + t * 64 + (tx << 2) + j] = acc[i][j] * 0.125f;
        __syncthreads();
    }

    // ---- Phase 2: softmax per query row (16 warps x 4 rows) ----
    const int warp = tid >> 5, lane = tid & 31;
    for (int r = 0; r < 4; r++) {
        const int iq = warp * 4 + r;
        const int q = q0 + iq;
        int jlo = iq;
        if (kstart + jlo < 0) jlo = -kstart;
        int jhi = iq + 2 * WIN;
        if (kstart + jhi > SEQ - 1) jhi = SEQ - 1 - kstart;
        float* row = &Ss[iq * PS];

        for (int j = lane; j < jlo; j += 32) row[j] = 0.f;
        for (int j = jhi + 1 + lane; j < KW; j += 32) row[j] = 0.f;

        float mx = -1e30f;
        for (int j = jlo + lane; j <= jhi; j += 32) mx = fmaxf(mx, row[j]);
#pragma unroll
        for (int o = 16; o; o >>= 1) mx = fmaxf(mx, __shfl_xor_sync(0xffffffffu, mx, o));

        float ssum = 0.f;
        for (int j = jlo + lane; j <= jhi; j += 32) {
            float e = __expf(row[j] - mx);
            row[j] = e;
            ssum += e;
        }
#pragma unroll
        for (int o = 16; o; o >>= 1) ssum += __shfl_xor_sync(0xffffffffu, ssum, o);
        const float inv = 1.f / ssum;

        if (writeAttn) {
            float* arow = attn + ((size_t)(b * NH + h) * SEQ + q) * SEQ;
            for (int j = jlo + lane; j <= jhi; j += 32) {
                float p = row[j] * inv;
                row[j] = p;
                arow[kstart + j] = p;
            }
        } else {
            for (int j = jlo + lane; j <= jhi; j += 32) row[j] *= inv;
        }
    }
    __syncthreads();

    // ---- Phase 3: ctx = P @ V ----
    float cacc[2][4];
#pragma unroll
    for (int i = 0; i < 2; i++)
#pragma unroll
        for (int j = 0; j < 4; j++) cacc[i][j] = 0.f;

    for (int t = 0; t < 5; t++) {
        const int kg0 = kstart + t * 64;
#pragma unroll
        for (int i = 0; i < 2; i++) {
            const int idx = tid + i * 512;
            const int row = idx >> 4;
            const int c4 = (idx & 15) << 2;
            const int kr = kg0 + row;
            float4 v = make_float4(0.f, 0.f, 0.f, 0.f);
            if (kr >= 0 && kr < SEQ)
                v = *(const float4*)(Vb + (size_t)kr * DH + c4);
            *(float4*)&Ts[row * LD + c4] = v;   // Vs[k][d]
        }
        __syncthreads();

#pragma unroll 8
        for (int kk = 0; kk < 64; kk++) {
            float4 bv = *(const float4*)&Ts[kk * LD + (tx << 2)];
            const int col = t * 64 + kk;
            float a0 = Ss[((ty << 1) + 0) * PS + col];
            float a1 = Ss[((ty << 1) + 1) * PS + col];
            cacc[0][0] += a0 * bv.x; cacc[0][1] += a0 * bv.y;
            cacc[0][2] += a0 * bv.z; cacc[0][3] += a0 * bv.w;
            cacc[1][0] += a1 * bv.x; cacc[1][1] += a1 * bv.y;
            cacc[1][2] += a1 * bv.z; cacc[1][3] += a1 * bv.w;
        }
        __syncthreads();
    }

#pragma unroll
    for (int i = 0; i < 2; i++) {
        const int q = q0 + (ty << 1) + i;
        float4 val = make_float4(cacc[i][0], cacc[i][1], cacc[i][2], cacc[i][3]);
        *(float4*)(ctx + (((size_t)b * SEQ + q) * NH + h) * DH + (tx << 2)) = val;
    }
}

// ---------------------------------------------------------------------------
extern "C" void kernel_launch(void* const* d_in, const int* in_sizes, int n_in,
                              void* d_out, int out_size)
{
    const float* x  = (const float*)d_in[0];
    const float* Wq = (const float*)d_in[1];
    const float* bq = (const float*)d_in[2];
    const float* Wk = (const float*)d_in[3];
    const float* bk = (const float*)d_in[4];
    const float* Wv = (const float*)d_in[5];
    const float* bv = (const float*)d_in[6];
    const float* Wo = (const float*)d_in[7];
    const float* bo = (const float*)d_in[8];
    float* out = (float*)d_out;

    float *Qp, *Kp, *Vp, *Cp;
    cudaGetSymbolAddress((void**)&Qp, g_Q);
    cudaGetSymbolAddress((void**)&Kp, g_K);
    cudaGetSymbolAddress((void**)&Vp, g_V);
    cudaGetSymbolAddress((void**)&Cp, g_ctx);

    __nv_bfloat16 *xhi, *xlo, *whi, *wlo, *chi, *clo;
    cudaGetSymbolAddress((void**)&xhi, g_xhi);
    cudaGetSymbolAddress((void**)&xlo, g_xlo);
    cudaGetSymbolAddress((void**)&whi, g_whi);
    cudaGetSymbolAddress((void**)&wlo, g_wlo);
    cudaGetSymbolAddress((void**)&chi, g_chi);
    cudaGetSymbolAddress((void**)&clo, g_clo);

    const size_t OUT_ELEMS  = (size_t)BATCH * SEQ * EMB;        // 4,194,304
    const size_t ATTN_ELEMS = (size_t)BATCH * NH * SEQ * SEQ;   // 134,217,728
    const int writeAttn = ((size_t)out_size >= OUT_ELEMS + ATTN_ELEMS) ? 1 : 0;
    float* attn_ptr = out + OUT_ELEMS;

    const int NX = BATCH * SEQ * EMB;   // 4,194,304
    const int NW = EMB * EMB;           // 1,048,576

    // fp32 -> split bf16 (x, then all 4 weights fused)
    split_bf16<<<NX / 1024, 256>>>(x, xhi, xlo, NX / 4);
    split_bf16_w4<<<dim3(NW / 1024, 4), 256>>>(Wq, Wk, Wv, Wo, whi, wlo, NW / 4);

    // mma.sync GEMMs
    constexpr int GSMEM = 2 * SSTAGE * 2;   // 81,920 B
    cudaFuncSetAttribute(gemm_mma_qkv, cudaFuncAttributeMaxDynamicSharedMemorySize, GSMEM);
    cudaFuncSetAttribute(gemm_mma_o,   cudaFuncAttributeMaxDynamicSharedMemorySize, GSMEM);

    // Fused QKV: grid (3*8, 32) = 768 CTAs
    gemm_mma_qkv<<<dim3(24, 32), 256, GSMEM>>>(xhi, xlo, whi, wlo, bq, bk, bv, Qp, Kp, Vp);

    // Zero the attn output region (masked entries are exactly 0)
    if (writeAttn)
        cudaMemsetAsync(attn_ptr, 0, ATTN_ELEMS * sizeof(float), 0);

    // Banded attention (512 threads)
    constexpr int SMEM = (2 * 64 * 68 + 64 * 321) * (int)sizeof(float);  // 116,992 B
    cudaFuncSetAttribute(attn_kernel, cudaFuncAttributeMaxDynamicSharedMemorySize, SMEM);
    attn_kernel<<<dim3(SEQ / 64, NH, BATCH), 512, SMEM>>>(Qp, Kp, Vp, Cp, attn_ptr, writeAttn);

    // Output projection
    split_bf16<<<NX / 1024, 256>>>(Cp, chi, clo, NX / 4);
    gemm_mma_o<<<dim3(8, 32), 256, GSMEM>>>(chi, clo, whi + 3 * (size_t)NW, wlo + 3 * (size_t)NW, bo, out);
}

// round 16
// speedup vs baseline: 1.2173x; 1.2173x over previous
#include <cuda_runtime.h>
#include <cuda_bf16.h>
#include <cstdint>

// Problem constants
#define BATCH 2
#define SEQ   2048
#define EMB   1024
#define NH    16
#define DH    64
#define WIN   128

// ---------------------------------------------------------------------------
// Scratch (static __device__ globals -- allocation-free)
// ---------------------------------------------------------------------------
__device__ __nv_bfloat16 g_qh[BATCH * NH * SEQ * DH];   // [B,H,S,dh] hi/lo
__device__ __nv_bfloat16 g_ql[BATCH * NH * SEQ * DH];
__device__ __nv_bfloat16 g_kh[BATCH * NH * SEQ * DH];
__device__ __nv_bfloat16 g_kl[BATCH * NH * SEQ * DH];
__device__ __nv_bfloat16 g_vh[BATCH * NH * SEQ * DH];
__device__ __nv_bfloat16 g_vl[BATCH * NH * SEQ * DH];

__device__ __nv_bfloat16 g_xhi[BATCH * SEQ * EMB];
__device__ __nv_bfloat16 g_xlo[BATCH * SEQ * EMB];
__device__ __nv_bfloat16 g_whi[4 * EMB * EMB];   // Wq,Wk,Wv,Wo hi parts
__device__ __nv_bfloat16 g_wlo[4 * EMB * EMB];
__device__ __nv_bfloat16 g_chi[BATCH * SEQ * EMB];   // ctx hi/lo (from attn)
__device__ __nv_bfloat16 g_clo[BATCH * SEQ * EMB];

// ---------------------------------------------------------------------------
// Helpers (all plain-target PTX: ldmatrix / mma.sync / cp.async)
// ---------------------------------------------------------------------------
__device__ __forceinline__ uint32_t smem_u32(const void* p) {
    uint32_t a;
    asm("{ .reg .u64 t; cvta.to.shared.u64 t, %1; cvt.u32.u64 %0, t; }"
        : "=r"(a) : "l"(p));
    return a;
}

__device__ __forceinline__ void cp_async16(uint32_t dst, const void* src) {
    asm volatile("cp.async.cg.shared.global [%0], [%1], 16;\n"
                 :: "r"(dst), "l"(src));
}

__device__ __forceinline__ void ldsm_x4(uint32_t addr, uint32_t* r) {
    asm volatile("ldmatrix.sync.aligned.m8n8.x4.shared.b16 {%0,%1,%2,%3}, [%4];"
                 : "=r"(r[0]), "=r"(r[1]), "=r"(r[2]), "=r"(r[3]) : "r"(addr));
}

__device__ __forceinline__ void ldsm_x2(uint32_t addr, uint32_t* r) {
    asm volatile("ldmatrix.sync.aligned.m8n8.x2.shared.b16 {%0,%1}, [%2];"
                 : "=r"(r[0]), "=r"(r[1]) : "r"(addr));
}

__device__ __forceinline__ void ldsm_x2t(uint32_t addr, uint32_t* r) {
    asm volatile("ldmatrix.sync.aligned.m8n8.x2.trans.shared.b16 {%0,%1}, [%2];"
                 : "=r"(r[0]), "=r"(r[1]) : "r"(addr));
}

__device__ __forceinline__ void mma16816(float* c, const uint32_t* a, const uint32_t* b) {
    asm volatile(
        "mma.sync.aligned.m16n8k16.row.col.f32.bf16.bf16.f32 "
        "{%0,%1,%2,%3}, {%4,%5,%6,%7}, {%8,%9}, {%0,%1,%2,%3};\n"
        : "+f"(c[0]), "+f"(c[1]), "+f"(c[2]), "+f"(c[3])
        : "r"(a[0]), "r"(a[1]), "r"(a[2]), "r"(a[3]), "r"(b[0]), "r"(b[1]));
}

// ---------------------------------------------------------------------------
// fp32 -> (hi, lo) bf16 split
// ---------------------------------------------------------------------------
__global__ void __launch_bounds__(256)
split_bf16(const float* __restrict__ in, __nv_bfloat16* __restrict__ hi,
           __nv_bfloat16* __restrict__ lo, int n4)
{
    int i = blockIdx.x * blockDim.x + threadIdx.x;
    if (i >= n4) return;
    float4 v = *(const float4*)(in + 4 * (size_t)i);
    __nv_bfloat16 h0 = __float2bfloat16(v.x);
    __nv_bfloat16 h1 = __float2bfloat16(v.y);
    __nv_bfloat16 h2 = __float2bfloat16(v.z);
    __nv_bfloat16 h3 = __float2bfloat16(v.w);
    __nv_bfloat16 l0 = __float2bfloat16(v.x - __bfloat162float(h0));
    __nv_bfloat16 l1 = __float2bfloat16(v.y - __bfloat162float(h1));
    __nv_bfloat16 l2 = __float2bfloat16(v.z - __bfloat162float(h2));
    __nv_bfloat16 l3 = __float2bfloat16(v.w - __bfloat162float(h3));
    __nv_bfloat162* hp = (__nv_bfloat162*)(hi + 4 * (size_t)i);
    __nv_bfloat162* lp = (__nv_bfloat162*)(lo + 4 * (size_t)i);
    hp[0] = __nv_bfloat162(h0, h1);
    hp[1] = __nv_bfloat162(h2, h3);
    lp[0] = __nv_bfloat162(l0, l1);
    lp[1] = __nv_bfloat162(l2, l3);
}

// Fused 4-matrix weight split (Wq,Wk,Wv,Wo) -- grid.y = matrix index
__global__ void __launch_bounds__(256)
split_bf16_w4(const float* __restrict__ w0, const float* __restrict__ w1,
              const float* __restrict__ w2, const float* __restrict__ w3,
              __nv_bfloat16* __restrict__ hi, __nv_bfloat16* __restrict__ lo, int n4)
{
    int i = blockIdx.x * blockDim.x + threadIdx.x;
    if (i >= n4) return;
    const int mat = blockIdx.y;
    const float* in = (mat == 0) ? w0 : (mat == 1) ? w1 : (mat == 2) ? w2 : w3;
    hi += (size_t)mat * (4 * (size_t)n4);
    lo += (size_t)mat * (4 * (size_t)n4);
    float4 v = *(const float4*)(in + 4 * (size_t)i);
    __nv_bfloat16 h0 = __float2bfloat16(v.x);
    __nv_bfloat16 h1 = __float2bfloat16(v.y);
    __nv_bfloat16 h2 = __float2bfloat16(v.z);
    __nv_bfloat16 h3 = __float2bfloat16(v.w);
    __nv_bfloat16 l0 = __float2bfloat16(v.x - __bfloat162float(h0));
    __nv_bfloat16 l1 = __float2bfloat16(v.y - __bfloat162float(h1));
    __nv_bfloat16 l2 = __float2bfloat16(v.z - __bfloat162float(h2));
    __nv_bfloat16 l3 = __float2bfloat16(v.w - __bfloat162float(h3));
    __nv_bfloat162* hp = (__nv_bfloat162*)(hi + 4 * (size_t)i);
    __nv_bfloat162* lp = (__nv_bfloat162*)(lo + 4 * (size_t)i);
    hp[0] = __nv_bfloat162(h0, h1);
    hp[1] = __nv_bfloat162(h2, h3);
    lp[0] = __nv_bfloat162(l0, l1);
    lp[1] = __nv_bfloat162(l2, l3);
}

// ---------------------------------------------------------------------------
// Split-bf16 tensor-core GEMM core (mma.sync m16n8k16)
// CTA tile 128x128, BK=32, 8 warps (warp tile 64x32), cp.async double buffer.
// MODE 0: fp32 row-major out;  MODE 1: bf16 hi/lo split out, scatter [B,H,S,dh]
// ---------------------------------------------------------------------------
#define LDT 40                      // bf16 elems per smem row (80B, LDSM conflict-free)
#define T_AH 0
#define T_AL (128 * LDT)
#define T_WH (2 * 128 * LDT)
#define T_WL (3 * 128 * LDT)
#define SSTAGE (4 * 128 * LDT)      // bf16 elems per stage (40960 B)

template <int MODE>
__device__ __forceinline__ void gemm_core(
    const __nv_bfloat16* __restrict__ Ahi, const __nv_bfloat16* __restrict__ Alo,
    const __nv_bfloat16* __restrict__ Whi, const __nv_bfloat16* __restrict__ Wlo,
    const float* __restrict__ bias, float* __restrict__ C,
    __nv_bfloat16* __restrict__ Ch, __nv_bfloat16* __restrict__ Cl,
    int m0, int n0, __nv_bfloat16* smem)
{
    constexpr int KD  = EMB;         // 1024
    constexpr int NCH = KD / 32;     // 32 K-chunks

    const uint32_t sbase = smem_u32(smem);
    const int tid  = threadIdx.x;
    const int wid  = tid >> 5;
    const int lane = tid & 31;

    const int glr = tid >> 2;            // 0..63
    const int glc = (tid & 3) * 8;       // bf16 col 0,8,16,24

    auto load_chunk = [&](int c, int stg) {
        const int k0 = c * 32;
        const uint32_t sb = sbase + (uint32_t)stg * (SSTAGE * 2);
#pragma unroll
        for (int p = 0; p < 2; p++) {
            const int row = glr + 64 * p;
            const size_t ga = (size_t)(m0 + row) * KD + k0 + glc;
            const size_t gw = (size_t)(n0 + row) * KD + k0 + glc;
            const uint32_t so = (uint32_t)(row * LDT + glc) * 2;
            cp_async16(sb + T_AH * 2 + so, Ahi + ga);
            cp_async16(sb + T_AL * 2 + so, Alo + ga);
            cp_async16(sb + T_WH * 2 + so, Whi + gw);
            cp_async16(sb + T_WL * 2 + so, Wlo + gw);
        }
    };

    float acc[4][4][4];
#pragma unroll
    for (int i = 0; i < 4; i++)
#pragma unroll
        for (int j = 0; j < 4; j++)
#pragma unroll
            for (int e = 0; e < 4; e++) acc[i][j][e] = 0.f;

    const int wm = wid >> 2;             // 0..1  (M)
    const int wn = wid & 3;              // 0..3  (N)
    const int mbase = wm * 64;
    const int nbase = wn * 32;

    const int a_row = mbase + (lane & 15);
    const int a_kad = 8 * (lane >> 4);
    const int b_row = nbase + (lane & 7);
    const int b_kad = 8 * ((lane >> 3) & 1);

    load_chunk(0, 0);
    asm volatile("cp.async.commit_group;\n");

    for (int c = 0; c < NCH; c++) {
        if (c + 1 < NCH) {
            load_chunk(c + 1, (c + 1) & 1);
            asm volatile("cp.async.commit_group;\n");
            asm volatile("cp.async.wait_group 1;\n");
        } else {
            asm volatile("cp.async.wait_group 0;\n");
        }
        __syncthreads();

        const uint32_t sb = sbase + (uint32_t)(c & 1) * (SSTAGE * 2);
#pragma unroll
        for (int ks = 0; ks < 2; ks++) {
            const int kk = ks * 16;
            uint32_t ah[4][4], al[4][4];
#pragma unroll
            for (int i = 0; i < 4; i++) {
                const uint32_t ao =
                    (uint32_t)((a_row + i * 16) * LDT + kk + a_kad) * 2;
                ldsm_x4(sb + T_AH * 2 + ao, ah[i]);
                ldsm_x4(sb + T_AL * 2 + ao, al[i]);
            }
#pragma unroll
            for (int j = 0; j < 4; j++) {
                uint32_t bh[2], bl[2];
                const uint32_t bo =
                    (uint32_t)((b_row + j * 8) * LDT + kk + b_kad) * 2;
                ldsm_x2(sb + T_WH * 2 + bo, bh);
                ldsm_x2(sb + T_WL * 2 + bo, bl);
#pragma unroll
                for (int i = 0; i < 4; i++) {
                    mma16816(acc[i][j], ah[i], bh);
                    mma16816(acc[i][j], ah[i], bl);
                    mma16816(acc[i][j], al[i], bh);
                }
            }
        }
        __syncthreads();
    }

    // ---- epilogue ----
    const int qr = lane >> 2;            // 0..7
    const int qc = (lane & 3) * 2;       // 0,2,4,6
#pragma unroll
    for (int i = 0; i < 4; i++) {
#pragma unroll
        for (int j = 0; j < 4; j++) {
            const int n = n0 + nbase + j * 8 + qc;
            const float b0 = bias[n], b1 = bias[n + 1];
#pragma unroll
            for (int half = 0; half < 2; half++) {
                const int m = m0 + mbase + i * 16 + qr + half * 8;
                const float vx = acc[i][j][half * 2 + 0] + b0;
                const float vy = acc[i][j][half * 2 + 1] + b1;
                if (MODE == 0) {
                    *(float2*)(C + (size_t)m * EMB + n) = make_float2(vx, vy);
                } else {
                    const int b  = m >> 11;     // SEQ = 2048
                    const int s  = m & 2047;
                    const int hh = n >> 6;      // DH = 64
                    const int d0 = n & 63;
                    const size_t off =
                        (((size_t)(b * NH + hh)) * SEQ + s) * DH + d0;
                    __nv_bfloat16 h0 = __float2bfloat16(vx);
                    __nv_bfloat16 h1 = __float2bfloat16(vy);
                    __nv_bfloat16 l0 = __float2bfloat16(vx - __bfloat162float(h0));
                    __nv_bfloat16 l1 = __float2bfloat16(vy - __bfloat162float(h1));
                    *(__nv_bfloat162*)(Ch + off) = __nv_bfloat162(h0, h1);
                    *(__nv_bfloat162*)(Cl + off) = __nv_bfloat162(l0, l1);
                }
            }
        }
    }
}

// Fused QKV projection: grid.x = 24 (mat*8 + nblock), grid.y = 32 (m blocks)
__global__ void __launch_bounds__(256, 2)
gemm_mma_qkv(const __nv_bfloat16* __restrict__ Ahi, const __nv_bfloat16* __restrict__ Alo,
             const __nv_bfloat16* __restrict__ WhiAll, const __nv_bfloat16* __restrict__ WloAll,
             const float* __restrict__ bq, const float* __restrict__ bk,
             const float* __restrict__ bv,
             __nv_bfloat16* __restrict__ Qh, __nv_bfloat16* __restrict__ Ql,
             __nv_bfloat16* __restrict__ Kh, __nv_bfloat16* __restrict__ Kl,
             __nv_bfloat16* __restrict__ Vh, __nv_bfloat16* __restrict__ Vl)
{
    extern __shared__ __nv_bfloat16 smem[];
    const int mat = blockIdx.x >> 3;
    const int n0  = (blockIdx.x & 7) * 128;
    const int m0  = blockIdx.y * 128;
    const __nv_bfloat16* Whi = WhiAll + (size_t)mat * (EMB * EMB);
    const __nv_bfloat16* Wlo = WloAll + (size_t)mat * (EMB * EMB);
    const float* bias = (mat == 0) ? bq : (mat == 1) ? bk : bv;
    __nv_bfloat16* Ch = (mat == 0) ? Qh : (mat == 1) ? Kh : Vh;
    __nv_bfloat16* Cl = (mat == 0) ? Ql : (mat == 1) ? Kl : Vl;
    gemm_core<1>(Ahi, Alo, Whi, Wlo, bias, nullptr, Ch, Cl, m0, n0, smem);
}

// Output projection (fp32 row-major out)
__global__ void __launch_bounds__(256, 2)
gemm_mma_o(const __nv_bfloat16* __restrict__ Ahi, const __nv_bfloat16* __restrict__ Alo,
           const __nv_bfloat16* __restrict__ Whi, const __nv_bfloat16* __restrict__ Wlo,
           const float* __restrict__ bias, float* __restrict__ C)
{
    extern __shared__ __nv_bfloat16 smem[];
    gemm_core<0>(Ahi, Alo, Whi, Wlo, bias, C, nullptr, nullptr,
                 blockIdx.y * 128, blockIdx.x * 128, smem);
}

// ---------------------------------------------------------------------------
// Banded attention on tensor cores (split-bf16 x3).
// One CTA = 64 queries of one (b,h); 320-key window; 256 threads, 8 warps.
// Phase 1: S = Q*K^T (HMMA) -> fp32 smem.  Phase 2: exact softmax, write attn
// band + P as bf16 hi/lo.  Phase 3: ctx = P*V (HMMA, ldmatrix.trans for V^T),
// written directly as bf16 hi/lo for the O-projection.
// ---------------------------------------------------------------------------
#define APS 328        // score row stride (floats / bf16 elems)
#define QLD 72         // Q/K/V tile row stride in bf16 (144B, LDSM conflict-free)
#define ATTN_SMEM (64 * APS * 4 + (4 * 64 * QLD + 2 * 64 * APS) * 2)  // 204,800 B

__global__ void __launch_bounds__(256, 1)
attn_tc(const __nv_bfloat16* __restrict__ Qh_, const __nv_bfloat16* __restrict__ Ql_,
        const __nv_bfloat16* __restrict__ Kh_, const __nv_bfloat16* __restrict__ Kl_,
        const __nv_bfloat16* __restrict__ Vh_, const __nv_bfloat16* __restrict__ Vl_,
        __nv_bfloat16* __restrict__ Ch, __nv_bfloat16* __restrict__ Cl,
        float* __restrict__ attn, int writeAttn)
{
    extern __shared__ char sm8[];
    float* Ss = (float*)sm8;                              // [64][APS] fp32 scores
    __nv_bfloat16* Qh = (__nv_bfloat16*)(Ss + 64 * APS);  // [64][QLD]
    __nv_bfloat16* Ql = Qh + 64 * QLD;
    __nv_bfloat16* Kh = Ql + 64 * QLD;                    // K tile; reused for V
    __nv_bfloat16* Kl = Kh + 64 * QLD;
    __nv_bfloat16* Ph = Kl + 64 * QLD;                    // [64][APS] P hi
    __nv_bfloat16* Pl = Ph + 64 * APS;                    // [64][APS] P lo

    const uint32_t sQh = smem_u32(Qh), sQl = smem_u32(Ql);
    const uint32_t sKh = smem_u32(Kh), sKl = smem_u32(Kl);
    const uint32_t sPh = smem_u32(Ph), sPl = smem_u32(Pl);

    const int tid  = threadIdx.x;
    const int wid  = tid >> 5;
    const int lane = tid & 31;
    const int wm = wid & 3;           // m-tile (4 x 16 rows)
    const int wn = wid >> 2;          // n-tile (2 x 32 cols)
    const int q0 = blockIdx.x * 64;
    const int h  = blockIdx.y;
    const int b  = blockIdx.z;
    const int kstart = q0 - WIN;
    const size_t base = ((size_t)(b * NH + h)) * SEQ * DH;

    // ---- load Q tile (hi/lo), 64 rows x 64 bf16 ----
    {
        const int c8 = (tid & 7) * 8;
#pragma unroll
        for (int p = 0; p < 2; p++) {
            const int r = (tid >> 3) + p * 32;
            const size_t g = base + (size_t)(q0 + r) * DH + c8;
            *(uint4*)(Qh + r * QLD + c8) = *(const uint4*)(Qh_ + g);
            *(uint4*)(Ql + r * QLD + c8) = *(const uint4*)(Ql_ + g);
        }
    }

    // ---- Phase 1: scores via HMMA, 5 key-groups of 64 ----
    const int qr = lane >> 2;
    const int qc = (lane & 3) * 2;
    for (int g = 0; g < 5; g++) {
        const int kg0 = kstart + g * 64;
        const int c8 = (tid & 7) * 8;
#pragma unroll
        for (int p = 0; p < 2; p++) {
            const int r = (tid >> 3) + p * 32;
            const int kr = kg0 + r;
            uint4 vh = make_uint4(0, 0, 0, 0), vl = make_uint4(0, 0, 0, 0);
            if (kr >= 0 && kr < SEQ) {
                const size_t ga = base + (size_t)kr * DH + c8;
                vh = *(const uint4*)(Kh_ + ga);
                vl = *(const uint4*)(Kl_ + ga);
            }
            *(uint4*)(Kh + r * QLD + c8) = vh;
            *(uint4*)(Kl + r * QLD + c8) = vl;
        }
        __syncthreads();

        float acc[4][4];
#pragma unroll
        for (int j = 0; j < 4; j++)
#pragma unroll
            for (int e = 0; e < 4; e++) acc[j][e] = 0.f;

#pragma unroll
        for (int ks = 0; ks < 4; ks++) {
            uint32_t ah[4], al[4];
            const uint32_t ao =
                (uint32_t)((wm * 16 + (lane & 15)) * QLD + ks * 16 + 8 * (lane >> 4)) * 2;
            ldsm_x4(sQh + ao, ah);
            ldsm_x4(sQl + ao, al);
#pragma unroll
            for (int j = 0; j < 4; j++) {
                uint32_t bh[2], bl[2];
                const uint32_t bo =
                    (uint32_t)((wn * 32 + j * 8 + (lane & 7)) * QLD + ks * 16 +
                               8 * ((lane >> 3) & 1)) * 2;
                ldsm_x2(sKh + bo, bh);
                ldsm_x2(sKl + bo, bl);
                mma16816(acc[j], ah, bh);
                mma16816(acc[j], ah, bl);
                mma16816(acc[j], al, bh);
            }
        }
#pragma unroll
        for (int j = 0; j < 4; j++) {
            const int col = g * 64 + wn * 32 + j * 8 + qc;
#pragma unroll
            for (int half = 0; half < 2; half++) {
                const int row = wm * 16 + qr + half * 8;
                *(float2*)&Ss[row * APS + col] =
                    make_float2(acc[j][half * 2] * 0.125f, acc[j][half * 2 + 1] * 0.125f);
            }
        }
        __syncthreads();
    }

    // ---- Phase 2: softmax per row; write attn band + P hi/lo ----
    for (int r = 0; r < 8; r++) {
        const int iq = wid * 8 + r;
        const int q = q0 + iq;
        int jlo = iq;
        if (kstart + jlo < 0) jlo = -kstart;
        int jhi = iq + 2 * WIN;
        if (kstart + jhi > SEQ - 1) jhi = SEQ - 1 - kstart;
        float* row = &Ss[iq * APS];
        __nv_bfloat16* ph = Ph + iq * APS;
        __nv_bfloat16* pl = Pl + iq * APS;

        for (int j = lane; j < jlo; j += 32) { ph[j] = __nv_bfloat16(0.f); pl[j] = __nv_bfloat16(0.f); }
        for (int j = jhi + 1 + lane; j < 320; j += 32) { ph[j] = __nv_bfloat16(0.f); pl[j] = __nv_bfloat16(0.f); }

        float mx = -1e30f;
        for (int j = jlo + lane; j <= jhi; j += 32) mx = fmaxf(mx, row[j]);
#pragma unroll
        for (int o = 16; o; o >>= 1) mx = fmaxf(mx, __shfl_xor_sync(0xffffffffu, mx, o));

        float ssum = 0.f;
        for (int j = jlo + lane; j <= jhi; j += 32) {
            float e = __expf(row[j] - mx);
            row[j] = e;
            ssum += e;
        }
#pragma unroll
        for (int o = 16; o; o >>= 1) ssum += __shfl_xor_sync(0xffffffffu, ssum, o);
        const float inv = 1.f / ssum;

        float* arow = attn + ((size_t)(b * NH + h) * SEQ + q) * SEQ;
        for (int j = jlo + lane; j <= jhi; j += 32) {
            const float p = row[j] * inv;
            const __nv_bfloat16 hi = __float2bfloat16(p);
            ph[j] = hi;
            pl[j] = __float2bfloat16(p - __bfloat162float(hi));
            if (writeAttn) arow[kstart + j] = p;
        }
    }
    __syncthreads();

    // ---- Phase 3: ctx = P*V via HMMA (V^T via ldmatrix.trans) ----
    float cacc[4][4];
#pragma unroll
    for (int j = 0; j < 4; j++)
#pragma unroll
        for (int e = 0; e < 4; e++) cacc[j][e] = 0.f;

    for (int g = 0; g < 5; g++) {
        const int kg0 = kstart + g * 64;
        const int c8 = (tid & 7) * 8;
#pragma unroll
        for (int p = 0; p < 2; p++) {
            const int r = (tid >> 3) + p * 32;
            const int kr = kg0 + r;
            uint4 vh = make_uint4(0, 0, 0, 0), vl = make_uint4(0, 0, 0, 0);
            if (kr >= 0 && kr < SEQ) {
                const size_t ga = base + (size_t)kr * DH + c8;
                vh = *(const uint4*)(Vh_ + ga);
                vl = *(const uint4*)(Vl_ + ga);
            }
            *(uint4*)(Kh + r * QLD + c8) = vh;   // reuse K tile space for V
            *(uint4*)(Kl + r * QLD + c8) = vl;
        }
        __syncthreads();

#pragma unroll
        for (int ks = 0; ks < 4; ks++) {
            uint32_t ah[4], al[4];
            const uint32_t ao =
                (uint32_t)((wm * 16 + (lane & 15)) * APS + g * 64 + ks * 16 +
                           8 * (lane >> 4)) * 2;
            ldsm_x4(sPh + ao, ah);
            ldsm_x4(sPl + ao, al);
#pragma unroll
            for (int j = 0; j < 4; j++) {
                uint32_t bh[2], bl[2];
                const uint32_t bo =
                    (uint32_t)((ks * 16 + (lane & 15)) * QLD + wn * 32 + j * 8) * 2;
                ldsm_x2t(sKh + bo, bh);
                ldsm_x2t(sKl + bo, bl);
                mma16816(cacc[j], ah, bh);
                mma16816(cacc[j], ah, bl);
                mma16816(cacc[j], al, bh);
            }
        }
        __syncthreads();
    }

    // ---- epilogue: write ctx as bf16 hi/lo directly ([B,S,D]) ----
#pragma unroll
    for (int j = 0; j < 4; j++) {
        const int dcol = wn * 32 + j * 8 + qc;
#pragma unroll
        for (int half = 0; half < 2; half++) {
            const int q = q0 + wm * 16 + qr + half * 8;
            const float vx = cacc[j][half * 2 + 0];
            const float vy = cacc[j][half * 2 + 1];
            const __nv_bfloat16 h0 = __float2bfloat16(vx);
            const __nv_bfloat16 h1 = __float2bfloat16(vy);
            const __nv_bfloat16 l0 = __float2bfloat16(vx - __bfloat162float(h0));
            const __nv_bfloat16 l1 = __float2bfloat16(vy - __bfloat162float(h1));
            const size_t off = ((size_t)b * SEQ + q) * EMB + h * 64 + dcol;
            *(__nv_bfloat162*)(Ch + off) = __nv_bfloat162(h0, h1);
            *(__nv_bfloat162*)(Cl + off) = __nv_bfloat162(l0, l1);
        }
    }
}

// ---------------------------------------------------------------------------
extern "C" void kernel_launch(void* const* d_in, const int* in_sizes, int n_in,
                              void* d_out, int out_size)
{
    const float* x  = (const float*)d_in[0];
    const float* Wq = (const float*)d_in[1];
    const float* bq = (const float*)d_in[2];
    const float* Wk = (const float*)d_in[3];
    const float* bk = (const float*)d_in[4];
    const float* Wv = (const float*)d_in[5];
    const float* bv = (const float*)d_in[6];
    const float* Wo = (const float*)d_in[7];
    const float* bo = (const float*)d_in[8];
    float* out = (float*)d_out;

    __nv_bfloat16 *qh, *ql, *kh, *kl, *vh, *vl;
    cudaGetSymbolAddress((void**)&qh, g_qh);
    cudaGetSymbolAddress((void**)&ql, g_ql);
    cudaGetSymbolAddress((void**)&kh, g_kh);
    cudaGetSymbolAddress((void**)&kl, g_kl);
    cudaGetSymbolAddress((void**)&vh, g_vh);
    cudaGetSymbolAddress((void**)&vl, g_vl);

    __nv_bfloat16 *xhi, *xlo, *whi, *wlo, *chi, *clo;
    cudaGetSymbolAddress((void**)&xhi, g_xhi);
    cudaGetSymbolAddress((void**)&xlo, g_xlo);
    cudaGetSymbolAddress((void**)&whi, g_whi);
    cudaGetSymbolAddress((void**)&wlo, g_wlo);
    cudaGetSymbolAddress((void**)&chi, g_chi);
    cudaGetSymbolAddress((void**)&clo, g_clo);

    const size_t OUT_ELEMS  = (size_t)BATCH * SEQ * EMB;        // 4,194,304
    const size_t ATTN_ELEMS = (size_t)BATCH * NH * SEQ * SEQ;   // 134,217,728
    const int writeAttn = ((size_t)out_size >= OUT_ELEMS + ATTN_ELEMS) ? 1 : 0;
    float* attn_ptr = out + OUT_ELEMS;

    const int NX = BATCH * SEQ * EMB;   // 4,194,304
    const int NW = EMB * EMB;           // 1,048,576

    // fp32 -> split bf16 (x, then all 4 weights fused)
    split_bf16<<<NX / 1024, 256>>>(x, xhi, xlo, NX / 4);
    split_bf16_w4<<<dim3(NW / 1024, 4), 256>>>(Wq, Wk, Wv, Wo, whi, wlo, NW / 4);

    // mma.sync GEMMs
    constexpr int GSMEM = 2 * SSTAGE * 2;   // 81,920 B
    cudaFuncSetAttribute(gemm_mma_qkv, cudaFuncAttributeMaxDynamicSharedMemorySize, GSMEM);
    cudaFuncSetAttribute(gemm_mma_o,   cudaFuncAttributeMaxDynamicSharedMemorySize, GSMEM);

    // Fused QKV: grid (3*8, 32) = 768 CTAs, emits bf16 hi/lo Q/K/V
    gemm_mma_qkv<<<dim3(24, 32), 256, GSMEM>>>(xhi, xlo, whi, wlo, bq, bk, bv,
                                               qh, ql, kh, kl, vh, vl);

    // Zero the attn output region (masked entries are exactly 0)
    if (writeAttn)
        cudaMemsetAsync(attn_ptr, 0, ATTN_ELEMS * sizeof(float), 0);

    // Tensor-core banded attention (writes ctx as bf16 hi/lo)
    cudaFuncSetAttribute(attn_tc, cudaFuncAttributeMaxDynamicSharedMemorySize, ATTN_SMEM);
    attn_tc<<<dim3(SEQ / 64, NH, BATCH), 256, ATTN_SMEM>>>(
        qh, ql, kh, kl, vh, vl, chi, clo, attn_ptr, writeAttn);

    // Output projection
    gemm_mma_o<<<dim3(8, 32), 256, GSMEM>>>(chi, clo, whi + 3 * (size_t)NW,
                                            wlo + 3 * (size_t)NW, bo, out);
}

// round 17
// speedup vs baseline: 1.2348x; 1.0144x over previous
#include <cuda_runtime.h>
#include <cuda_bf16.h>
#include <cstdint>

// Problem constants
#define BATCH 2
#define SEQ   2048
#define EMB   1024
#define NH    16
#define DH    64
#define WIN   128

// ---------------------------------------------------------------------------
// Scratch (static __device__ globals -- allocation-free)
// ---------------------------------------------------------------------------
__device__ __nv_bfloat16 g_qh[BATCH * NH * SEQ * DH];   // [B,H,S,dh] hi/lo
__device__ __nv_bfloat16 g_ql[BATCH * NH * SEQ * DH];
__device__ __nv_bfloat16 g_kh[BATCH * NH * SEQ * DH];
__device__ __nv_bfloat16 g_kl[BATCH * NH * SEQ * DH];
__device__ __nv_bfloat16 g_vh[BATCH * NH * SEQ * DH];
__device__ __nv_bfloat16 g_vl[BATCH * NH * SEQ * DH];

__device__ __nv_bfloat16 g_xhi[BATCH * SEQ * EMB];
__device__ __nv_bfloat16 g_xlo[BATCH * SEQ * EMB];
__device__ __nv_bfloat16 g_whi[4 * EMB * EMB];   // Wq,Wk,Wv,Wo hi parts
__device__ __nv_bfloat16 g_wlo[4 * EMB * EMB];
__device__ __nv_bfloat16 g_chi[BATCH * SEQ * EMB];   // ctx hi/lo (from attn)
__device__ __nv_bfloat16 g_clo[BATCH * SEQ * EMB];

// ---------------------------------------------------------------------------
// Helpers (all plain-target PTX: ldmatrix / mma.sync / cp.async)
// ---------------------------------------------------------------------------
__device__ __forceinline__ uint32_t smem_u32(const void* p) {
    uint32_t a;
    asm("{ .reg .u64 t; cvta.to.shared.u64 t, %1; cvt.u32.u64 %0, t; }"
        : "=r"(a) : "l"(p));
    return a;
}

__device__ __forceinline__ void cp_async16(uint32_t dst, const void* src) {
    asm volatile("cp.async.cg.shared.global [%0], [%1], 16;\n"
                 :: "r"(dst), "l"(src));
}

// cp.async with source-size predicate: srcsz==0 -> pure zero-fill
__device__ __forceinline__ void cp_async16z(uint32_t dst, const void* src, int srcsz) {
    asm volatile("cp.async.cg.shared.global [%0], [%1], 16, %2;\n"
                 :: "r"(dst), "l"(src), "r"(srcsz));
}

__device__ __forceinline__ void cp_commit() {
    asm volatile("cp.async.commit_group;\n");
}

__device__ __forceinline__ void ldsm_x4(uint32_t addr, uint32_t* r) {
    asm volatile("ldmatrix.sync.aligned.m8n8.x4.shared.b16 {%0,%1,%2,%3}, [%4];"
                 : "=r"(r[0]), "=r"(r[1]), "=r"(r[2]), "=r"(r[3]) : "r"(addr));
}

__device__ __forceinline__ void ldsm_x2(uint32_t addr, uint32_t* r) {
    asm volatile("ldmatrix.sync.aligned.m8n8.x2.shared.b16 {%0,%1}, [%2];"
                 : "=r"(r[0]), "=r"(r[1]) : "r"(addr));
}

__device__ __forceinline__ void ldsm_x2t(uint32_t addr, uint32_t* r) {
    asm volatile("ldmatrix.sync.aligned.m8n8.x2.trans.shared.b16 {%0,%1}, [%2];"
                 : "=r"(r[0]), "=r"(r[1]) : "r"(addr));
}

__device__ __forceinline__ void mma16816(float* c, const uint32_t* a, const uint32_t* b) {
    asm volatile(
        "mma.sync.aligned.m16n8k16.row.col.f32.bf16.bf16.f32 "
        "{%0,%1,%2,%3}, {%4,%5,%6,%7}, {%8,%9}, {%0,%1,%2,%3};\n"
        : "+f"(c[0]), "+f"(c[1]), "+f"(c[2]), "+f"(c[3])
        : "r"(a[0]), "r"(a[1]), "r"(a[2]), "r"(a[3]), "r"(b[0]), "r"(b[1]));
}

// ---------------------------------------------------------------------------
// fp32 -> (hi, lo) bf16 split
// ---------------------------------------------------------------------------
__global__ void __launch_bounds__(256)
split_bf16(const float* __restrict__ in, __nv_bfloat16* __restrict__ hi,
           __nv_bfloat16* __restrict__ lo, int n4)
{
    int i = blockIdx.x * blockDim.x + threadIdx.x;
    if (i >= n4) return;
    float4 v = *(const float4*)(in + 4 * (size_t)i);
    __nv_bfloat16 h0 = __float2bfloat16(v.x);
    __nv_bfloat16 h1 = __float2bfloat16(v.y);
    __nv_bfloat16 h2 = __float2bfloat16(v.z);
    __nv_bfloat16 h3 = __float2bfloat16(v.w);
    __nv_bfloat16 l0 = __float2bfloat16(v.x - __bfloat162float(h0));
    __nv_bfloat16 l1 = __float2bfloat16(v.y - __bfloat162float(h1));
    __nv_bfloat16 l2 = __float2bfloat16(v.z - __bfloat162float(h2));
    __nv_bfloat16 l3 = __float2bfloat16(v.w - __bfloat162float(h3));
    __nv_bfloat162* hp = (__nv_bfloat162*)(hi + 4 * (size_t)i);
    __nv_bfloat162* lp = (__nv_bfloat162*)(lo + 4 * (size_t)i);
    hp[0] = __nv_bfloat162(h0, h1);
    hp[1] = __nv_bfloat162(h2, h3);
    lp[0] = __nv_bfloat162(l0, l1);
    lp[1] = __nv_bfloat162(l2, l3);
}

// Fused 4-matrix weight split (Wq,Wk,Wv,Wo) -- grid.y = matrix index
__global__ void __launch_bounds__(256)
split_bf16_w4(const float* __restrict__ w0, const float* __restrict__ w1,
              const float* __restrict__ w2, const float* __restrict__ w3,
              __nv_bfloat16* __restrict__ hi, __nv_bfloat16* __restrict__ lo, int n4)
{
    int i = blockIdx.x * blockDim.x + threadIdx.x;
    if (i >= n4) return;
    const int mat = blockIdx.y;
    const float* in = (mat == 0) ? w0 : (mat == 1) ? w1 : (mat == 2) ? w2 : w3;
    hi += (size_t)mat * (4 * (size_t)n4);
    lo += (size_t)mat * (4 * (size_t)n4);
    float4 v = *(const float4*)(in + 4 * (size_t)i);
    __nv_bfloat16 h0 = __float2bfloat16(v.x);
    __nv_bfloat16 h1 = __float2bfloat16(v.y);
    __nv_bfloat16 h2 = __float2bfloat16(v.z);
    __nv_bfloat16 h3 = __float2bfloat16(v.w);
    __nv_bfloat16 l0 = __float2bfloat16(v.x - __bfloat162float(h0));
    __nv_bfloat16 l1 = __float2bfloat16(v.y - __bfloat162float(h1));
    __nv_bfloat16 l2 = __float2bfloat16(v.z - __bfloat162float(h2));
    __nv_bfloat16 l3 = __float2bfloat16(v.w - __bfloat162float(h3));
    __nv_bfloat162* hp = (__nv_bfloat162*)(hi + 4 * (size_t)i);
    __nv_bfloat162* lp = (__nv_bfloat162*)(lo + 4 * (size_t)i);
    hp[0] = __nv_bfloat162(h0, h1);
    hp[1] = __nv_bfloat162(h2, h3);
    lp[0] = __nv_bfloat162(l0, l1);
    lp[1] = __nv_bfloat162(l2, l3);
}

// ---------------------------------------------------------------------------
// Split-bf16 tensor-core GEMM core (mma.sync m16n8k16)
// CTA tile 128x128, BK=32, 8 warps (warp tile 64x32), cp.async double buffer.
// MODE 0: fp32 row-major out;  MODE 1: bf16 hi/lo split out, scatter [B,H,S,dh]
// ---------------------------------------------------------------------------
#define LDT 40                      // bf16 elems per smem row (80B, LDSM conflict-free)
#define T_AH 0
#define T_AL (128 * LDT)
#define T_WH (2 * 128 * LDT)
#define T_WL (3 * 128 * LDT)
#define SSTAGE (4 * 128 * LDT)      // bf16 elems per stage (40960 B)

template <int MODE>
__device__ __forceinline__ void gemm_core(
    const __nv_bfloat16* __restrict__ Ahi, const __nv_bfloat16* __restrict__ Alo,
    const __nv_bfloat16* __restrict__ Whi, const __nv_bfloat16* __restrict__ Wlo,
    const float* __restrict__ bias, float* __restrict__ C,
    __nv_bfloat16* __restrict__ Ch, __nv_bfloat16* __restrict__ Cl,
    int m0, int n0, __nv_bfloat16* smem)
{
    constexpr int KD  = EMB;         // 1024
    constexpr int NCH = KD / 32;     // 32 K-chunks

    const uint32_t sbase = smem_u32(smem);
    const int tid  = threadIdx.x;
    const int wid  = tid >> 5;
    const int lane = tid & 31;

    const int glr = tid >> 2;            // 0..63
    const int glc = (tid & 3) * 8;       // bf16 col 0,8,16,24

    auto load_chunk = [&](int c, int stg) {
        const int k0 = c * 32;
        const uint32_t sb = sbase + (uint32_t)stg * (SSTAGE * 2);
#pragma unroll
        for (int p = 0; p < 2; p++) {
            const int row = glr + 64 * p;
            const size_t ga = (size_t)(m0 + row) * KD + k0 + glc;
            const size_t gw = (size_t)(n0 + row) * KD + k0 + glc;
            const uint32_t so = (uint32_t)(row * LDT + glc) * 2;
            cp_async16(sb + T_AH * 2 + so, Ahi + ga);
            cp_async16(sb + T_AL * 2 + so, Alo + ga);
            cp_async16(sb + T_WH * 2 + so, Whi + gw);
            cp_async16(sb + T_WL * 2 + so, Wlo + gw);
        }
    };

    float acc[4][4][4];
#pragma unroll
    for (int i = 0; i < 4; i++)
#pragma unroll
        for (int j = 0; j < 4; j++)
#pragma unroll
            for (int e = 0; e < 4; e++) acc[i][j][e] = 0.f;

    const int wm = wid >> 2;             // 0..1  (M)
    const int wn = wid & 3;              // 0..3  (N)
    const int mbase = wm * 64;
    const int nbase = wn * 32;

    const int a_row = mbase + (lane & 15);
    const int a_kad = 8 * (lane >> 4);
    const int b_row = nbase + (lane & 7);
    const int b_kad = 8 * ((lane >> 3) & 1);

    load_chunk(0, 0);
    cp_commit();

    for (int c = 0; c < NCH; c++) {
        if (c + 1 < NCH) {
            load_chunk(c + 1, (c + 1) & 1);
            cp_commit();
            asm volatile("cp.async.wait_group 1;\n");
        } else {
            asm volatile("cp.async.wait_group 0;\n");
        }
        __syncthreads();

        const uint32_t sb = sbase + (uint32_t)(c & 1) * (SSTAGE * 2);
#pragma unroll
        for (int ks = 0; ks < 2; ks++) {
            const int kk = ks * 16;
            uint32_t ah[4][4], al[4][4];
#pragma unroll
            for (int i = 0; i < 4; i++) {
                const uint32_t ao =
                    (uint32_t)((a_row + i * 16) * LDT + kk + a_kad) * 2;
                ldsm_x4(sb + T_AH * 2 + ao, ah[i]);
                ldsm_x4(sb + T_AL * 2 + ao, al[i]);
            }
#pragma unroll
            for (int j = 0; j < 4; j++) {
                uint32_t bh[2], bl[2];
                const uint32_t bo =
                    (uint32_t)((b_row + j * 8) * LDT + kk + b_kad) * 2;
                ldsm_x2(sb + T_WH * 2 + bo, bh);
                ldsm_x2(sb + T_WL * 2 + bo, bl);
#pragma unroll
                for (int i = 0; i < 4; i++) {
                    mma16816(acc[i][j], ah[i], bh);
                    mma16816(acc[i][j], ah[i], bl);
                    mma16816(acc[i][j], al[i], bh);
                }
            }
        }
        __syncthreads();
    }

    // ---- epilogue ----
    const int qr = lane >> 2;            // 0..7
    const int qc = (lane & 3) * 2;       // 0,2,4,6
#pragma unroll
    for (int i = 0; i < 4; i++) {
#pragma unroll
        for (int j = 0; j < 4; j++) {
            const int n = n0 + nbase + j * 8 + qc;
            const float b0 = bias[n], b1 = bias[n + 1];
#pragma unroll
            for (int half = 0; half < 2; half++) {
                const int m = m0 + mbase + i * 16 + qr + half * 8;
                const float vx = acc[i][j][half * 2 + 0] + b0;
                const float vy = acc[i][j][half * 2 + 1] + b1;
                if (MODE == 0) {
                    *(float2*)(C + (size_t)m * EMB + n) = make_float2(vx, vy);
                } else {
                    const int b  = m >> 11;     // SEQ = 2048
                    const int s  = m & 2047;
                    const int hh = n >> 6;      // DH = 64
                    const int d0 = n & 63;
                    const size_t off =
                        (((size_t)(b * NH + hh)) * SEQ + s) * DH + d0;
                    __nv_bfloat16 h0 = __float2bfloat16(vx);
                    __nv_bfloat16 h1 = __float2bfloat16(vy);
                    __nv_bfloat16 l0 = __float2bfloat16(vx - __bfloat162float(h0));
                    __nv_bfloat16 l1 = __float2bfloat16(vy - __bfloat162float(h1));
                    *(__nv_bfloat162*)(Ch + off) = __nv_bfloat162(h0, h1);
                    *(__nv_bfloat162*)(Cl + off) = __nv_bfloat162(l0, l1);
                }
            }
        }
    }
}

// Fused QKV projection: grid.x = 24 (mat*8 + nblock), grid.y = 32 (m blocks)
__global__ void __launch_bounds__(256, 2)
gemm_mma_qkv(const __nv_bfloat16* __restrict__ Ahi, const __nv_bfloat16* __restrict__ Alo,
             const __nv_bfloat16* __restrict__ WhiAll, const __nv_bfloat16* __restrict__ WloAll,
             const float* __restrict__ bq, const float* __restrict__ bk,
             const float* __restrict__ bv,
             __nv_bfloat16* __restrict__ Qh, __nv_bfloat16* __restrict__ Ql,
             __nv_bfloat16* __restrict__ Kh, __nv_bfloat16* __restrict__ Kl,
             __nv_bfloat16* __restrict__ Vh, __nv_bfloat16* __restrict__ Vl)
{
    extern __shared__ __nv_bfloat16 smem[];
    const int mat = blockIdx.x >> 3;
    const int n0  = (blockIdx.x & 7) * 128;
    const int m0  = blockIdx.y * 128;
    const __nv_bfloat16* Whi = WhiAll + (size_t)mat * (EMB * EMB);
    const __nv_bfloat16* Wlo = WloAll + (size_t)mat * (EMB * EMB);
    const float* bias = (mat == 0) ? bq : (mat == 1) ? bk : bv;
    __nv_bfloat16* Ch = (mat == 0) ? Qh : (mat == 1) ? Kh : Vh;
    __nv_bfloat16* Cl = (mat == 0) ? Ql : (mat == 1) ? Kl : Vl;
    gemm_core<1>(Ahi, Alo, Whi, Wlo, bias, nullptr, Ch, Cl, m0, n0, smem);
}

// Output projection (fp32 row-major out)
__global__ void __launch_bounds__(256, 2)
gemm_mma_o(const __nv_bfloat16* __restrict__ Ahi, const __nv_bfloat16* __restrict__ Alo,
           const __nv_bfloat16* __restrict__ Whi, const __nv_bfloat16* __restrict__ Wlo,
           const float* __restrict__ bias, float* __restrict__ C)
{
    extern __shared__ __nv_bfloat16 smem[];
    gemm_core<0>(Ahi, Alo, Whi, Wlo, bias, C, nullptr, nullptr,
                 blockIdx.y * 128, blockIdx.x * 128, smem);
}

// ---------------------------------------------------------------------------
// Banded attention on tensor cores (split-bf16 x3) with cp.async pipeline.
// One CTA = 64 queries of one (b,h); 320-key window; 256 threads, 8 warps.
// Score buffer Ss[64][APS] fp32 is overwritten in-place by softmax with
// packed (bf16hi | bf16lo<<16) P values; phase-3 A fragments are rebuilt
// with LDS.32 + PRMT. K/V tiles double-buffered with cp.async; V prefetched
// during softmax.
// ---------------------------------------------------------------------------
#define APS 330        // score row stride (4B words; 16-row fragment reads conflict-free)
#define QLD 72         // Q/K/V tile row stride in bf16 (144B, LDSM conflict-free)
#define ATTN_SMEM (64 * APS * 4 + (2 + 4) * 64 * QLD * 2)   // 139,776 B

__global__ void __launch_bounds__(256, 1)
attn_tc(const __nv_bfloat16* __restrict__ Qh_, const __nv_bfloat16* __restrict__ Ql_,
        const __nv_bfloat16* __restrict__ Kh_, const __nv_bfloat16* __restrict__ Kl_,
        const __nv_bfloat16* __restrict__ Vh_, const __nv_bfloat16* __restrict__ Vl_,
        __nv_bfloat16* __restrict__ Ch, __nv_bfloat16* __restrict__ Cl,
        float* __restrict__ attn, int writeAttn)
{
    extern __shared__ char sm8[];
    float*    Ss = (float*)sm8;                    // [64][APS] scores -> packed P
    uint32_t* Su = (uint32_t*)sm8;
    __nv_bfloat16* Qh = (__nv_bfloat16*)(Ss + 64 * APS);   // [64][QLD]
    __nv_bfloat16* Ql = Qh + 64 * QLD;
    __nv_bfloat16* KB = Ql + 64 * QLD;             // [2 stages][hi/lo][64*QLD]

    const uint32_t sQh = smem_u32(Qh), sQl = smem_u32(Ql);
    const uint32_t sKB = smem_u32(KB);
    auto kb = [&](int st, int hl) -> uint32_t {
        return sKB + (uint32_t)((st * 2 + hl) * 64 * QLD * 2);
    };

    const int tid  = threadIdx.x;
    const int wid  = tid >> 5;
    const int lane = tid & 31;
    const int wm = wid & 3;           // m-tile (4 x 16 rows)
    const int wn = wid >> 2;          // n-tile (2 x 32 cols)
    const int q0 = blockIdx.x * 64;
    const int h  = blockIdx.y;
    const int b  = blockIdx.z;
    const int kstart = q0 - WIN;
    const size_t base = ((size_t)(b * NH + h)) * SEQ * DH;

    const int lr = tid >> 3;          // 0..31
    const int lc = (tid & 7) * 8;     // bf16 col 0..56

    auto issue_tile = [&](const __nv_bfloat16* Hsrc, const __nv_bfloat16* Lsrc,
                          int g, int st) {
        const int kg0 = kstart + g * 64;
#pragma unroll
        for (int p = 0; p < 2; p++) {
            const int r  = lr + p * 32;
            const int kr = kg0 + r;
            const int ok = (kr >= 0 && kr < SEQ) ? 16 : 0;
            const size_t ga = base + (size_t)(ok ? kr : 0) * DH + lc;
            const uint32_t so = (uint32_t)(r * QLD + lc) * 2;
            cp_async16z(kb(st, 0) + so, Hsrc + ga, ok);
            cp_async16z(kb(st, 1) + so, Lsrc + ga, ok);
        }
    };

    // ---- prologue: Q + K0 (group A), K1 (group B) ----
    {
#pragma unroll
        for (int p = 0; p < 2; p++) {
            const int r = lr + p * 32;
            const size_t ga = base + (size_t)(q0 + r) * DH + lc;
            const uint32_t so = (uint32_t)(r * QLD + lc) * 2;
            cp_async16(sQh + so, Qh_ + ga);
            cp_async16(sQl + so, Ql_ + ga);
        }
        issue_tile(Kh_, Kl_, 0, 0);
        cp_commit();
        issue_tile(Kh_, Kl_, 1, 1);
        cp_commit();
    }

    const int qr = lane >> 2;
    const int qc = (lane & 3) * 2;

    // ---- Phase 1: scores via HMMA, 5 key-groups, double-buffered ----
    for (int g = 0; g < 5; g++) {
        asm volatile("cp.async.wait_group 1;\n");
        __syncthreads();
        const int st = g & 1;

        float acc[4][4];
#pragma unroll
        for (int j = 0; j < 4; j++)
#pragma unroll
            for (int e = 0; e < 4; e++) acc[j][e] = 0.f;

#pragma unroll
        for (int ks = 0; ks < 4; ks++) {
            uint32_t ah[4], al[4];
            const uint32_t ao =
                (uint32_t)((wm * 16 + (lane & 15)) * QLD + ks * 16 + 8 * (lane >> 4)) * 2;
            ldsm_x4(sQh + ao, ah);
            ldsm_x4(sQl + ao, al);
#pragma unroll
            for (int j = 0; j < 4; j++) {
                uint32_t bh[2], bl[2];
                const uint32_t bo =
                    (uint32_t)((wn * 32 + j * 8 + (lane & 7)) * QLD + ks * 16 +
                               8 * ((lane >> 3) & 1)) * 2;
                ldsm_x2(kb(st, 0) + bo, bh);
                ldsm_x2(kb(st, 1) + bo, bl);
                mma16816(acc[j], ah, bh);
                mma16816(acc[j], ah, bl);
                mma16816(acc[j], al, bh);
            }
        }
#pragma unroll
        for (int j = 0; j < 4; j++) {
            const int col = g * 64 + wn * 32 + j * 8 + qc;
#pragma unroll
            for (int half = 0; half < 2; half++) {
                const int row = wm * 16 + qr + half * 8;
                *(float2*)&Ss[row * APS + col] =
                    make_float2(acc[j][half * 2] * 0.125f, acc[j][half * 2 + 1] * 0.125f);
            }
        }
        __syncthreads();

        if (g < 3)       { issue_tile(Kh_, Kl_, g + 2, st); cp_commit(); }
        else if (g == 3) { issue_tile(Vh_, Vl_, 0, st);     cp_commit(); }  // V0 -> stage1
        else             { issue_tile(Vh_, Vl_, 1, st);     cp_commit(); }  // V1 -> stage0
    }

    // ---- Phase 2: softmax per row; write attn band; pack P in-place ----
    for (int r = 0; r < 8; r++) {
        const int iq = wid * 8 + r;
        const int q = q0 + iq;
        int jlo = iq;
        if (kstart + jlo < 0) jlo = -kstart;
        int jhi = iq + 2 * WIN;
        if (kstart + jhi > SEQ - 1) jhi = SEQ - 1 - kstart;
        float* row = &Ss[iq * APS];
        uint32_t* prow = &Su[iq * APS];

        for (int j = lane; j < jlo; j += 32) prow[j] = 0u;
        for (int j = jhi + 1 + lane; j < 320; j += 32) prow[j] = 0u;

        float mx = -1e30f;
        for (int j = jlo + lane; j <= jhi; j += 32) mx = fmaxf(mx, row[j]);
#pragma unroll
        for (int o = 16; o; o >>= 1) mx = fmaxf(mx, __shfl_xor_sync(0xffffffffu, mx, o));

        float ssum = 0.f;
        for (int j = jlo + lane; j <= jhi; j += 32) {
            float e = __expf(row[j] - mx);
            row[j] = e;
            ssum += e;
        }
#pragma unroll
        for (int o = 16; o; o >>= 1) ssum += __shfl_xor_sync(0xffffffffu, ssum, o);
        const float inv = 1.f / ssum;

        float* arow = attn + ((size_t)(b * NH + h) * SEQ + q) * SEQ;
        for (int j = jlo + lane; j <= jhi; j += 32) {
            const float p = row[j] * inv;
            const __nv_bfloat16 hi = __float2bfloat16(p);
            const __nv_bfloat16 lo = __float2bfloat16(p - __bfloat162float(hi));
            prow[j] = ((uint32_t)__bfloat16_as_ushort(lo) << 16) |
                      (uint32_t)__bfloat16_as_ushort(hi);
            if (writeAttn) arow[kstart + j] = p;
        }
    }
    __syncthreads();

    // ---- Phase 3: ctx = P*V via HMMA; A from packed Su, V via ldmatrix.trans ----
    float cacc[4][4];
#pragma unroll
    for (int j = 0; j < 4; j++)
#pragma unroll
        for (int e = 0; e < 4; e++) cacc[j][e] = 0.f;

    const int r0 = wm * 16 + (lane >> 2);

    for (int g = 0; g < 5; g++) {
        if (g == 4) asm volatile("cp.async.wait_group 0;\n");
        else        asm volatile("cp.async.wait_group 1;\n");
        __syncthreads();
        const int st = (g + 1) & 1;

#pragma unroll
        for (int ks = 0; ks < 4; ks++) {
            const int c0 = g * 64 + ks * 16 + (lane & 3) * 2;
            const uint32_t w00 = Su[r0 * APS + c0],       w01 = Su[r0 * APS + c0 + 1];
            const uint32_t w10 = Su[(r0 + 8) * APS + c0], w11 = Su[(r0 + 8) * APS + c0 + 1];
            const uint32_t w02 = Su[r0 * APS + c0 + 8],   w03 = Su[r0 * APS + c0 + 9];
            const uint32_t w12 = Su[(r0 + 8) * APS + c0 + 8], w13 = Su[(r0 + 8) * APS + c0 + 9];
            uint32_t ah[4], al[4];
            ah[0] = __byte_perm(w00, w01, 0x5410); al[0] = __byte_perm(w00, w01, 0x7632);
            ah[1] = __byte_perm(w10, w11, 0x5410); al[1] = __byte_perm(w10, w11, 0x7632);
            ah[2] = __byte_perm(w02, w03, 0x5410); al[2] = __byte_perm(w02, w03, 0x7632);
            ah[3] = __byte_perm(w12, w13, 0x5410); al[3] = __byte_perm(w12, w13, 0x7632);
#pragma unroll
            for (int j = 0; j < 4; j++) {
                uint32_t bh[2], bl[2];
                const uint32_t bo =
                    (uint32_t)((ks * 16 + (lane & 15)) * QLD + wn * 32 + j * 8) * 2;
                ldsm_x2t(kb(st, 0) + bo, bh);
                ldsm_x2t(kb(st, 1) + bo, bl);
                mma16816(cacc[j], ah, bh);
                mma16816(cacc[j], ah, bl);
                mma16816(cacc[j], al, bh);
            }
        }
        __syncthreads();
        if (g < 3) { issue_tile(Vh_, Vl_, g + 2, st); cp_commit(); }
    }

    // ---- epilogue: write ctx as bf16 hi/lo directly ([B,S,D]) ----
#pragma unroll
    for (int j = 0; j < 4; j++) {
        const int dcol = wn * 32 + j * 8 + qc;
#pragma unroll
        for (int half = 0; half < 2; half++) {
            const int q = q0 + wm * 16 + qr + half * 8;
            const float vx = cacc[j][half * 2 + 0];
            const float vy = cacc[j][half * 2 + 1];
            const __nv_bfloat16 h0 = __float2bfloat16(vx);
            const __nv_bfloat16 h1 = __float2bfloat16(vy);
            const __nv_bfloat16 l0 = __float2bfloat16(vx - __bfloat162float(h0));
            const __nv_bfloat16 l1 = __float2bfloat16(vy - __bfloat162float(h1));
            const size_t off = ((size_t)b * SEQ + q) * EMB + h * 64 + dcol;
            *(__nv_bfloat162*)(Ch + off) = __nv_bfloat162(h0, h1);
            *(__nv_bfloat162*)(Cl + off) = __nv_bfloat162(l0, l1);
        }
    }
}

// ---------------------------------------------------------------------------
extern "C" void kernel_launch(void* const* d_in, const int* in_sizes, int n_in,
                              void* d_out, int out_size)
{
    const float* x  = (const float*)d_in[0];
    const float* Wq = (const float*)d_in[1];
    const float* bq = (const float*)d_in[2];
    const float* Wk = (const float*)d_in[3];
    const float* bk = (const float*)d_in[4];
    const float* Wv = (const float*)d_in[5];
    const float* bv = (const float*)d_in[6];
    const float* Wo = (const float*)d_in[7];
    const float* bo = (const float*)d_in[8];
    float* out = (float*)d_out;

    __nv_bfloat16 *qh, *ql, *kh, *kl, *vh, *vl;
    cudaGetSymbolAddress((void**)&qh, g_qh);
    cudaGetSymbolAddress((void**)&ql, g_ql);
    cudaGetSymbolAddress((void**)&kh, g_kh);
    cudaGetSymbolAddress((void**)&kl, g_kl);
    cudaGetSymbolAddress((void**)&vh, g_vh);
    cudaGetSymbolAddress((void**)&vl, g_vl);

    __nv_bfloat16 *xhi, *xlo, *whi, *wlo, *chi, *clo;
    cudaGetSymbolAddress((void**)&xhi, g_xhi);
    cudaGetSymbolAddress((void**)&xlo, g_xlo);
    cudaGetSymbolAddress((void**)&whi, g_whi);
    cudaGetSymbolAddress((void**)&wlo, g_wlo);
    cudaGetSymbolAddress((void**)&chi, g_chi);
    cudaGetSymbolAddress((void**)&clo, g_clo);

    const size_t OUT_ELEMS  = (size_t)BATCH * SEQ * EMB;        // 4,194,304
    const size_t ATTN_ELEMS = (size_t)BATCH * NH * SEQ * SEQ;   // 134,217,728
    const int writeAttn = ((size_t)out_size >= OUT_ELEMS + ATTN_ELEMS) ? 1 : 0;
    float* attn_ptr = out + OUT_ELEMS;

    const int NX = BATCH * SEQ * EMB;   // 4,194,304
    const int NW = EMB * EMB;           // 1,048,576

    // Side stream for overlapping the big attn-region memset with the QKV GEMM.
    // Created once (host-side resource; identical captured work every call).
    static cudaStream_t s_fork = nullptr;
    static cudaEvent_t  s_ev1 = nullptr, s_ev2 = nullptr;
    if (s_fork == nullptr) {
        cudaStreamCreateWithFlags(&s_fork, cudaStreamNonBlocking);
        cudaEventCreateWithFlags(&s_ev1, cudaEventDisableTiming);
        cudaEventCreateWithFlags(&s_ev2, cudaEventDisableTiming);
    }

    if (writeAttn) {
        cudaEventRecord(s_ev1, 0);
        cudaStreamWaitEvent(s_fork, s_ev1, 0);
        cudaMemsetAsync(attn_ptr, 0, ATTN_ELEMS * sizeof(float), s_fork);
        cudaEventRecord(s_ev2, s_fork);
    }

    // fp32 -> split bf16 (x, then all 4 weights fused)
    split_bf16<<<NX / 1024, 256>>>(x, xhi, xlo, NX / 4);
    split_bf16_w4<<<dim3(NW / 1024, 4), 256>>>(Wq, Wk, Wv, Wo, whi, wlo, NW / 4);

    // mma.sync GEMMs
    constexpr int GSMEM = 2 * SSTAGE * 2;   // 81,920 B
    cudaFuncSetAttribute(gemm_mma_qkv, cudaFuncAttributeMaxDynamicSharedMemorySize, GSMEM);
    cudaFuncSetAttribute(gemm_mma_o,   cudaFuncAttributeMaxDynamicSharedMemorySize, GSMEM);

    // Fused QKV: grid (3*8, 32) = 768 CTAs, emits bf16 hi/lo Q/K/V
    gemm_mma_qkv<<<dim3(24, 32), 256, GSMEM>>>(xhi, xlo, whi, wlo, bq, bk, bv,
                                               qh, ql, kh, kl, vh, vl);

    // Join: attn kernel writes into the memset region
    if (writeAttn) cudaStreamWaitEvent(0, s_ev2, 0);

    // Tensor-core banded attention (writes ctx as bf16 hi/lo)
    cudaFuncSetAttribute(attn_tc, cudaFuncAttributeMaxDynamicSharedMemorySize, ATTN_SMEM);
    attn_tc<<<dim3(SEQ / 64, NH, BATCH), 256, ATTN_SMEM>>>(
        qh, ql, kh, kl, vh, vl, chi, clo, attn_ptr, writeAttn);

    // Output projection
    gemm_mma_o<<<dim3(8, 32), 256, GSMEM>>>(chi, clo, whi + 3 * (size_t)NW,
                                            wlo + 3 * (size_t)NW, bo, out);
}